// round 7
// baseline (speedup 1.0000x reference)
#include <cuda_runtime.h>
#include <cuda_fp8.h>
#include <cuda_bf16.h>
#include <cstdint>

// ============================================================
// Scratch (device globals: allocation-guard-safe)
// ============================================================
static __device__ uint8_t g_xq[8192ull * 4096ull];     // quantized activations
static __device__ uint8_t g_wq[4096ull * 4096ull];     // re-encoded weights (f32/bf16 modes)
static __device__ float   g_in_scale[8192];            // per-token scales
static __device__ int     g_wmode;                     // 0=raw fp8 bytes, 1=f32, 2=bf16

// ============================================================
// Helpers
// ============================================================
#define SW128(o) ((o) ^ (((o) >> 3) & 0x70))

__device__ __forceinline__ uint32_t smem_u32(const void* p) {
    uint32_t a;
    asm("{ .reg .u64 t; cvta.to.shared.u64 t, %1; cvt.u32.u64 %0, t; }"
        : "=r"(a) : "l"(p));
    return a;
}

__device__ __forceinline__ void cp16(uint32_t dst, const void* src) {
    asm volatile("cp.async.cg.shared.global [%0], [%1], 16;\n"
                 :: "r"(dst), "l"(src));
}

__device__ __forceinline__ void ldsm_x4(uint32_t& r0, uint32_t& r1,
                                        uint32_t& r2, uint32_t& r3, uint32_t addr) {
    asm volatile("ldmatrix.sync.aligned.m8n8.x4.shared.b16 {%0,%1,%2,%3}, [%4];"
                 : "=r"(r0), "=r"(r1), "=r"(r2), "=r"(r3) : "r"(addr));
}

// FP8 e4m3 MMA, m16n8k32, f32 accumulate
__device__ __forceinline__ void mma_fp8(float* d, const uint32_t* a, const uint32_t* b) {
    asm volatile(
        "mma.sync.aligned.m16n8k32.row.col.f32.e4m3.e4m3.f32 "
        "{%0,%1,%2,%3}, {%4,%5,%6,%7}, {%8,%9}, {%0,%1,%2,%3};"
        : "+f"(d[0]), "+f"(d[1]), "+f"(d[2]), "+f"(d[3])
        : "r"(a[0]), "r"(a[1]), "r"(a[2]), "r"(a[3]), "r"(b[0]), "r"(b[1]));
}

// ============================================================
// Kernel 0a: detect weight storage format
// ============================================================
__global__ void detect_kernel(const void* w) {
    __shared__ int okf, bigf, okh, bigh;
    int t = threadIdx.x;
    if (t == 0) { okf = 0; bigf = 0; okh = 0; bigh = 0; }
    __syncthreads();

    float vf = reinterpret_cast<const float*>(w)[t];
    float af = fabsf(vf);
    if (af <= 448.0f) {
        atomicAdd(&okf, 1);
        if (af >= 0.5f) atomicAdd(&bigf, 1);
    }
    float vh = __bfloat162float(reinterpret_cast<const __nv_bfloat16*>(w)[t]);
    float ah = fabsf(vh);
    if (ah <= 448.0f) {
        atomicAdd(&okh, 1);
        if (ah >= 0.5f) atomicAdd(&bigh, 1);
    }
    __syncthreads();
    if (t == 0) {
        int m = 0;
        if (okf == 256 && bigf >= 128)      m = 1;
        else if (okh == 256 && bigh >= 128) m = 2;
        g_wmode = m;
    }
}

// ============================================================
// Kernel 0b: re-encode weights to e4m3 bytes (modes 1/2 only)
// ============================================================
__global__ __launch_bounds__(256) void prep_kernel(const void* w, long long total) {
    int mode = g_wmode;
    if (mode == 0) return;
    long long e0 = (long long)(blockIdx.x * 256 + threadIdx.x) * 16;
    if (e0 >= total) return;

    uint8_t b[16];
    if (mode == 1) {
        const float4* f4 = reinterpret_cast<const float4*>(w) + (e0 >> 2);
#pragma unroll
        for (int j = 0; j < 4; j++) {
            float4 v = f4[j];
            b[4 * j + 0] = __nv_fp8_e4m3(v.x).__x;
            b[4 * j + 1] = __nv_fp8_e4m3(v.y).__x;
            b[4 * j + 2] = __nv_fp8_e4m3(v.z).__x;
            b[4 * j + 3] = __nv_fp8_e4m3(v.w).__x;
        }
    } else {
        const __nv_bfloat16* h = reinterpret_cast<const __nv_bfloat16*>(w) + e0;
#pragma unroll
        for (int j = 0; j < 16; j++)
            b[j] = __nv_fp8_e4m3(__bfloat162float(h[j])).__x;
    }
    *reinterpret_cast<uint4*>(g_wq + e0) = *reinterpret_cast<const uint4*>(b);
}

// ============================================================
// Kernel 1: per-token dynamic FP8 quantization
// ============================================================
__global__ __launch_bounds__(256) void quant_kernel(const float* __restrict__ x, int K) {
    int row = blockIdx.x;
    const float4* xr = reinterpret_cast<const float4*>(x + (size_t)row * K);
    int t = threadIdx.x;
    int nv = K >> 10;

    float vals[16];
    float amax = 0.0f;
#pragma unroll
    for (int i = 0; i < 4; i++) {
        if (i < nv) {
            float4 v = xr[t + (i << 8)];
            vals[4 * i + 0] = v.x; vals[4 * i + 1] = v.y;
            vals[4 * i + 2] = v.z; vals[4 * i + 3] = v.w;
            amax = fmaxf(amax, fmaxf(fmaxf(fabsf(v.x), fabsf(v.y)),
                                     fmaxf(fabsf(v.z), fabsf(v.w))));
        }
    }
#pragma unroll
    for (int o = 16; o > 0; o >>= 1)
        amax = fmaxf(amax, __shfl_xor_sync(0xffffffffu, amax, o));

    __shared__ float red[8];
    __shared__ float s_scale;
    if ((t & 31) == 0) red[t >> 5] = amax;
    __syncthreads();
    if (t == 0) {
        float a = red[0];
#pragma unroll
        for (int i = 1; i < 8; i++) a = fmaxf(a, red[i]);
        float s = fmaxf(a / 448.0f, 1e-12f);
        s_scale = s;
        g_in_scale[row] = s;
    }
    __syncthreads();
    float s = s_scale;

    uint32_t* ow = reinterpret_cast<uint32_t*>(g_xq + (size_t)row * K);
#pragma unroll
    for (int i = 0; i < 4; i++) {
        if (i < nv) {
            uint32_t p = 0;
#pragma unroll
            for (int j = 0; j < 4; j++) {
                float q = vals[4 * i + j] / s;
                __nv_fp8_e4m3 f8 = __nv_fp8_e4m3(q);
                p |= ((uint32_t)f8.__x) << (8 * j);
            }
            ow[t + (i << 8)] = p;
        }
    }
}

// ============================================================
// Kernel 2: FP8 GEMM via mma.sync.m16n8k32.e4m3
//   CTA 128x256, 8 warps (2x4), warp tile 64x64, 1 CTA/SM
//   4-stage cp.async pipeline, SW128 SMEM, paired ldsm.x4
//   ks-level fragment software pipeline (double-buffered regs)
// ============================================================
#define TM 128
#define TN 256
#define KC 128
#define STAGE_BYTES ((TM + TN) * KC)                 // 49152
#define NSTAGE 4
#define SMEM_TOTAL (NSTAGE * STAGE_BYTES)            // 196608

__global__ __launch_bounds__(256, 1) void gemm_kernel(
    const uint8_t* __restrict__ Win, const float* __restrict__ wscale,
    const float* __restrict__ bias, float* __restrict__ out,
    int T, int K, int N)
{
    extern __shared__ __align__(1024) char smem[];
    uint32_t smem_base = smem_u32(smem);
    int tid = threadIdx.x;
    int wid = tid >> 5;
    int lane = tid & 31;

    const uint8_t* W = g_wmode ? g_wq : Win;

    int m0 = blockIdx.y * TM;
    int n0 = blockIdx.x * TN;
    int nc = K >> 7;            // 128B K-chunks

    int wm = wid >> 2;          // 0..1  (64-row slab)
    int wn = wid & 3;           // 0..3  (64-col slab)

    // ---- hoisted global-load addressing ----
    int lr = tid >> 3;                      // 0..31
    int lc = (tid & 7) * 16;
    uint32_t sw = SW128((uint32_t)(lr * KC + lc));   // additive over +i*4096
    const uint8_t* aPtr = g_xq + (size_t)(m0 + lr) * K + lc;
    const uint8_t* bPtr = W + (size_t)(n0 + lr) * K + lc;
    size_t rs32 = (size_t)32 * K;

#define LOAD_STAGE(s_, kc_) do {                                               \
        uint32_t ad = smem_base + (s_) * STAGE_BYTES + sw;                     \
        uint32_t bd = ad + TM * KC;                                            \
        const uint8_t* ag = aPtr + (size_t)(kc_) * KC;                         \
        const uint8_t* bg = bPtr + (size_t)(kc_) * KC;                         \
        _Pragma("unroll")                                                      \
        for (int i = 0; i < 4; i++)                                            \
            cp16(ad + (uint32_t)(i * 4096), ag + i * rs32);                    \
        _Pragma("unroll")                                                      \
        for (int i = 0; i < 8; i++)                                            \
            cp16(bd + (uint32_t)(i * 4096), bg + i * rs32);                    \
        asm volatile("cp.async.commit_group;\n" ::);                           \
    } while (0)

    // ---- hoisted ldmatrix addressing (algebraic SW128) ----
    int a_row = wm * 64 + (lane & 15);
    uint32_t a_roff = (uint32_t)(a_row * KC);
    uint32_t a_sel = (uint32_t)((lane >> 4) << 4);
    uint32_t kxor = (uint32_t)((lane & 7) << 4);      // row&7 == lane&7 for A and B
    int b_rowl = (lane & 7) + ((lane >> 4) << 3);
    uint32_t b_roff = (uint32_t)((wn * 64 + b_rowl) * KC);
    uint32_t b_sel = (uint32_t)(((lane >> 3) & 1) << 4);

    uint32_t a_k[4], b_k[4];
#pragma unroll
    for (int ks = 0; ks < 4; ks++) {
        a_k[ks] = ((uint32_t)(ks * 32) + a_sel) ^ kxor;
        b_k[ks] = ((uint32_t)(ks * 32) + b_sel) ^ kxor;
    }

    float acc[4][8][4];
#pragma unroll
    for (int i = 0; i < 4; i++)
#pragma unroll
        for (int j = 0; j < 8; j++)
#pragma unroll
            for (int k = 0; k < 4; k++) acc[i][j][k] = 0.0f;

    // fragment double buffers (fits: acc 128 + frags 64 + addr ~30 < 255 regs)
    uint32_t af[2][4][4];
    uint32_t bf[2][8][2];

#define LOAD_FRAGS(buf_, ks_) do {                                             \
        _Pragma("unroll")                                                      \
        for (int mt = 0; mt < 4; mt++)                                         \
            ldsm_x4(af[buf_][mt][0], af[buf_][mt][1],                          \
                    af[buf_][mt][2], af[buf_][mt][3],                          \
                    a_ln + (uint32_t)(mt * 16 * KC) + a_k[ks_]);               \
        _Pragma("unroll")                                                      \
        for (int j = 0; j < 4; j++)                                            \
            ldsm_x4(bf[buf_][2 * j][0],     bf[buf_][2 * j][1],                \
                    bf[buf_][2 * j + 1][0], bf[buf_][2 * j + 1][1],            \
                    b_ln + (uint32_t)(j * 16 * KC) + b_k[ks_]);                \
    } while (0)

    // prologue: 3 stages in flight
    LOAD_STAGE(0, 0);
    LOAD_STAGE(1, 1);
    LOAD_STAGE(2, 2);

    for (int kc = 0; kc < nc; kc++) {
        int s = kc & (NSTAGE - 1);
        int trailing = nc - 1 - kc;
        if (trailing >= 2)      asm volatile("cp.async.wait_group 2;\n" ::: "memory");
        else if (trailing == 1) asm volatile("cp.async.wait_group 1;\n" ::: "memory");
        else                    asm volatile("cp.async.wait_group 0;\n" ::: "memory");
        __syncthreads();    // stage s ready; all warps done reading stage (kc+3)&3

        if (kc + 3 < nc) LOAD_STAGE((kc + 3) & (NSTAGE - 1), kc + 3);

        uint32_t a_ln = smem_base + s * STAGE_BYTES + a_roff;
        uint32_t b_ln = smem_base + s * STAGE_BYTES + TM * KC + b_roff;

        LOAD_FRAGS(0, 0);
#pragma unroll
        for (int ks = 0; ks < 4; ks++) {        // unrolled: ks compile-time
            if (ks < 3) {
                // issue next ks' fragment loads BEFORE this ks' MMA burst
                if ((ks & 1) == 0) LOAD_FRAGS(1, ks + 1);
                else               LOAD_FRAGS(0, ks + 1);
            }
            const int cur = ks & 1;
#pragma unroll
            for (int mt = 0; mt < 4; mt++)
#pragma unroll
                for (int nt = 0; nt < 8; nt++)
                    mma_fp8(acc[mt][nt], af[cur][mt], bf[cur][nt]);
        }
    }

    // ---- epilogue: dequant (in_scale * weight_scale) + bias ----
    int gid = lane >> 2;
    int tig = lane & 3;
#pragma unroll
    for (int mt = 0; mt < 4; mt++) {
        int r0 = m0 + wm * 64 + mt * 16 + gid;
        int r1 = r0 + 8;
        float is0 = g_in_scale[r0];
        float is1 = g_in_scale[r1];
        float* o0 = out + (size_t)r0 * N + n0;
        float* o1 = out + (size_t)r1 * N + n0;
#pragma unroll
        for (int nt = 0; nt < 8; nt++) {
            int c = wn * 64 + nt * 8 + tig * 2;
            float2 ws = *reinterpret_cast<const float2*>(wscale + n0 + c);
            float2 bi = *reinterpret_cast<const float2*>(bias + n0 + c);
            float2 v0, v1;
            v0.x = acc[mt][nt][0] * is0 * ws.x + bi.x;
            v0.y = acc[mt][nt][1] * is0 * ws.y + bi.y;
            v1.x = acc[mt][nt][2] * is1 * ws.x + bi.x;
            v1.y = acc[mt][nt][3] * is1 * ws.y + bi.y;
            *reinterpret_cast<float2*>(o0 + c) = v0;
            *reinterpret_cast<float2*>(o1 + c) = v1;
        }
    }
}

// ============================================================
// Launch
// ============================================================
extern "C" void kernel_launch(void* const* d_in, const int* in_sizes, int n_in,
                              void* d_out, int out_size)
{
    const float*   x  = (const float*)d_in[0];
    const void*    w  = d_in[1];
    const float*   ws = (const float*)d_in[2];
    const float*   b  = (const float*)d_in[3];
    float* out = (float*)d_out;

    int N = in_sizes[2];
    long long WE = in_sizes[1];
    int K = (int)(WE / N);
    int T = in_sizes[0] / K;

    detect_kernel<<<1, 256>>>(w);
    prep_kernel<<<(int)((WE / 16 + 255) / 256), 256>>>(w, WE);
    quant_kernel<<<T, 256>>>(x, K);

    cudaFuncSetAttribute(gemm_kernel, cudaFuncAttributeMaxDynamicSharedMemorySize,
                         SMEM_TOTAL);
    dim3 grid(N / TN, T / TM);
    gemm_kernel<<<grid, 256, SMEM_TOTAL>>>((const uint8_t*)w, ws, b, out, T, K, N);
}

// round 8
// speedup vs baseline: 1.0483x; 1.0483x over previous
#include <cuda_runtime.h>
#include <cuda_fp8.h>
#include <cuda_bf16.h>
#include <cstdint>

// ============================================================
// Scratch (device globals: allocation-guard-safe)
// ============================================================
static __device__ uint8_t g_xq[8192ull * 4096ull];     // quantized activations
static __device__ uint8_t g_wq[4096ull * 4096ull];     // re-encoded weights (f32/bf16 modes)
static __device__ float   g_in_scale[8192];            // per-token scales
static __device__ int     g_wmode;                     // 0=raw fp8 bytes, 1=f32, 2=bf16

// ============================================================
// Helpers
// ============================================================
#define SW128(o) ((o) ^ (((o) >> 3) & 0x70))

__device__ __forceinline__ uint32_t smem_u32(const void* p) {
    uint32_t a;
    asm("{ .reg .u64 t; cvta.to.shared.u64 t, %1; cvt.u32.u64 %0, t; }"
        : "=r"(a) : "l"(p));
    return a;
}

__device__ __forceinline__ void cp16(uint32_t dst, const void* src) {
    asm volatile("cp.async.cg.shared.global [%0], [%1], 16;\n"
                 :: "r"(dst), "l"(src));
}

__device__ __forceinline__ void ldsm_x4(uint32_t& r0, uint32_t& r1,
                                        uint32_t& r2, uint32_t& r3, uint32_t addr) {
    asm volatile("ldmatrix.sync.aligned.m8n8.x4.shared.b16 {%0,%1,%2,%3}, [%4];"
                 : "=r"(r0), "=r"(r1), "=r"(r2), "=r"(r3) : "r"(addr));
}

// FP8 e4m3 MMA, m16n8k32, f32 accumulate
__device__ __forceinline__ void mma_fp8(float* d, const uint32_t* a, const uint32_t* b) {
    asm volatile(
        "mma.sync.aligned.m16n8k32.row.col.f32.e4m3.e4m3.f32 "
        "{%0,%1,%2,%3}, {%4,%5,%6,%7}, {%8,%9}, {%0,%1,%2,%3};"
        : "+f"(d[0]), "+f"(d[1]), "+f"(d[2]), "+f"(d[3])
        : "r"(a[0]), "r"(a[1]), "r"(a[2]), "r"(a[3]), "r"(b[0]), "r"(b[1]));
}

// ============================================================
// Kernel 0a: detect weight storage format
// ============================================================
__global__ void detect_kernel(const void* w) {
    __shared__ int okf, bigf, okh, bigh;
    int t = threadIdx.x;
    if (t == 0) { okf = 0; bigf = 0; okh = 0; bigh = 0; }
    __syncthreads();

    float vf = reinterpret_cast<const float*>(w)[t];
    float af = fabsf(vf);
    if (af <= 448.0f) {
        atomicAdd(&okf, 1);
        if (af >= 0.5f) atomicAdd(&bigf, 1);
    }
    float vh = __bfloat162float(reinterpret_cast<const __nv_bfloat16*>(w)[t]);
    float ah = fabsf(vh);
    if (ah <= 448.0f) {
        atomicAdd(&okh, 1);
        if (ah >= 0.5f) atomicAdd(&bigh, 1);
    }
    __syncthreads();
    if (t == 0) {
        int m = 0;
        if (okf == 256 && bigf >= 128)      m = 1;
        else if (okh == 256 && bigh >= 128) m = 2;
        g_wmode = m;
    }
}

// ============================================================
// Kernel 0b: re-encode weights to e4m3 bytes (modes 1/2 only)
// ============================================================
__global__ __launch_bounds__(256) void prep_kernel(const void* w, long long total) {
    int mode = g_wmode;
    if (mode == 0) return;
    long long e0 = (long long)(blockIdx.x * 256 + threadIdx.x) * 16;
    if (e0 >= total) return;

    uint8_t b[16];
    if (mode == 1) {
        const float4* f4 = reinterpret_cast<const float4*>(w) + (e0 >> 2);
#pragma unroll
        for (int j = 0; j < 4; j++) {
            float4 v = f4[j];
            b[4 * j + 0] = __nv_fp8_e4m3(v.x).__x;
            b[4 * j + 1] = __nv_fp8_e4m3(v.y).__x;
            b[4 * j + 2] = __nv_fp8_e4m3(v.z).__x;
            b[4 * j + 3] = __nv_fp8_e4m3(v.w).__x;
        }
    } else {
        const __nv_bfloat16* h = reinterpret_cast<const __nv_bfloat16*>(w) + e0;
#pragma unroll
        for (int j = 0; j < 16; j++)
            b[j] = __nv_fp8_e4m3(__bfloat162float(h[j])).__x;
    }
    *reinterpret_cast<uint4*>(g_wq + e0) = *reinterpret_cast<const uint4*>(b);
}

// ============================================================
// Kernel 1: per-token dynamic FP8 quantization
// ============================================================
__global__ __launch_bounds__(256) void quant_kernel(const float* __restrict__ x, int K) {
    int row = blockIdx.x;
    const float4* xr = reinterpret_cast<const float4*>(x + (size_t)row * K);
    int t = threadIdx.x;
    int nv = K >> 10;

    float vals[16];
    float amax = 0.0f;
#pragma unroll
    for (int i = 0; i < 4; i++) {
        if (i < nv) {
            float4 v = xr[t + (i << 8)];
            vals[4 * i + 0] = v.x; vals[4 * i + 1] = v.y;
            vals[4 * i + 2] = v.z; vals[4 * i + 3] = v.w;
            amax = fmaxf(amax, fmaxf(fmaxf(fabsf(v.x), fabsf(v.y)),
                                     fmaxf(fabsf(v.z), fabsf(v.w))));
        }
    }
#pragma unroll
    for (int o = 16; o > 0; o >>= 1)
        amax = fmaxf(amax, __shfl_xor_sync(0xffffffffu, amax, o));

    __shared__ float red[8];
    __shared__ float s_scale;
    if ((t & 31) == 0) red[t >> 5] = amax;
    __syncthreads();
    if (t == 0) {
        float a = red[0];
#pragma unroll
        for (int i = 1; i < 8; i++) a = fmaxf(a, red[i]);
        float s = fmaxf(a / 448.0f, 1e-12f);
        s_scale = s;
        g_in_scale[row] = s;
    }
    __syncthreads();
    float s = s_scale;

    uint32_t* ow = reinterpret_cast<uint32_t*>(g_xq + (size_t)row * K);
#pragma unroll
    for (int i = 0; i < 4; i++) {
        if (i < nv) {
            uint32_t p = 0;
#pragma unroll
            for (int j = 0; j < 4; j++) {
                float q = vals[4 * i + j] / s;
                __nv_fp8_e4m3 f8 = __nv_fp8_e4m3(q);
                p |= ((uint32_t)f8.__x) << (8 * j);
            }
            ow[t + (i << 8)] = p;
        }
    }
}

// ============================================================
// Kernel 2: FP8 GEMM via mma.sync.m16n8k32.e4m3
//   CTA 128x256, 8 warps (2x4), warp tile 64x64, 1 CTA/SM
//   2-stage x 256B-K pipeline (2 chunks/stage), SW128 SMEM
//   One __syncthreads per 256 MMAs/warp (16 total)
// ============================================================
#define TM 128
#define TN 256
#define KC 128
#define CHUNK_BYTES ((TM + TN) * KC)                  // 49152
#define STAGE_BYTES (2 * CHUNK_BYTES)                 // 98304
#define SMEM_TOTAL (2 * STAGE_BYTES)                  // 196608

__global__ __launch_bounds__(256, 1) void gemm_kernel(
    const uint8_t* __restrict__ Win, const float* __restrict__ wscale,
    const float* __restrict__ bias, float* __restrict__ out,
    int T, int K, int N)
{
    extern __shared__ __align__(1024) char smem[];
    uint32_t smem_base = smem_u32(smem);
    int tid = threadIdx.x;
    int wid = tid >> 5;
    int lane = tid & 31;

    const uint8_t* W = g_wmode ? g_wq : Win;

    int m0 = blockIdx.y * TM;
    int n0 = blockIdx.x * TN;
    int nc2 = K >> 8;           // 256B K-superchunks (16 for K=4096)

    int wm = wid >> 2;          // 0..1  (64-row slab)
    int wn = wid & 3;           // 0..3  (64-col slab)

    // ---- hoisted global-load addressing ----
    int lr = tid >> 3;                      // 0..31
    int lc = (tid & 7) * 16;
    uint32_t sw = SW128((uint32_t)(lr * KC + lc));   // additive over +i*4096
    const uint8_t* aPtr = g_xq + (size_t)(m0 + lr) * K + lc;
    const uint8_t* bPtr = W + (size_t)(n0 + lr) * K + lc;
    size_t rs32 = (size_t)32 * K;

    // loads one 96KB stage = two 128B-K chunks; single commit group
#define LOAD_STAGE(s_, kc2_) do {                                              \
        _Pragma("unroll")                                                      \
        for (int c = 0; c < 2; c++) {                                          \
            uint32_t ad = smem_base + (s_) * STAGE_BYTES + c * CHUNK_BYTES + sw; \
            uint32_t bd = ad + TM * KC;                                        \
            const uint8_t* ag = aPtr + (size_t)(2 * (kc2_) + c) * KC;          \
            const uint8_t* bg = bPtr + (size_t)(2 * (kc2_) + c) * KC;          \
            _Pragma("unroll")                                                  \
            for (int i = 0; i < 4; i++)                                        \
                cp16(ad + (uint32_t)(i * 4096), ag + i * rs32);                \
            _Pragma("unroll")                                                  \
            for (int i = 0; i < 8; i++)                                        \
                cp16(bd + (uint32_t)(i * 4096), bg + i * rs32);                \
        }                                                                      \
        asm volatile("cp.async.commit_group;\n" ::);                           \
    } while (0)

    // ---- hoisted ldmatrix addressing (algebraic SW128) ----
    int a_row = wm * 64 + (lane & 15);
    uint32_t a_roff = (uint32_t)(a_row * KC);
    uint32_t a_sel = (uint32_t)((lane >> 4) << 4);
    uint32_t kxor = (uint32_t)((lane & 7) << 4);      // row&7 == lane&7 for A and B
    int b_rowl = (lane & 7) + ((lane >> 4) << 3);
    uint32_t b_roff = (uint32_t)((wn * 64 + b_rowl) * KC);
    uint32_t b_sel = (uint32_t)(((lane >> 3) & 1) << 4);

    uint32_t a_k[4], b_k[4];
#pragma unroll
    for (int ks = 0; ks < 4; ks++) {
        a_k[ks] = ((uint32_t)(ks * 32) + a_sel) ^ kxor;
        b_k[ks] = ((uint32_t)(ks * 32) + b_sel) ^ kxor;
    }

    float acc[4][8][4];
#pragma unroll
    for (int i = 0; i < 4; i++)
#pragma unroll
        for (int j = 0; j < 8; j++)
#pragma unroll
            for (int k = 0; k < 4; k++) acc[i][j][k] = 0.0f;

    // prologue: stage 0 in flight
    LOAD_STAGE(0, 0);

    for (int kc2 = 0; kc2 < nc2; kc2++) {
        int s = kc2 & 1;
        asm volatile("cp.async.wait_group 0;\n" ::: "memory");
        __syncthreads();    // stage s ready; stage s^1 fully consumed (prev iter)

        if (kc2 + 1 < nc2) LOAD_STAGE(s ^ 1, kc2 + 1);

#pragma unroll
        for (int c = 0; c < 2; c++) {
            uint32_t cbase = smem_base + s * STAGE_BYTES + c * CHUNK_BYTES;
            uint32_t a_ln = cbase + a_roff;
            uint32_t b_ln = cbase + TM * KC + b_roff;

#pragma unroll
            for (int ks = 0; ks < 4; ks++) {
                uint32_t af[4][4];
#pragma unroll
                for (int mt = 0; mt < 4; mt++)
                    ldsm_x4(af[mt][0], af[mt][1], af[mt][2], af[mt][3],
                            a_ln + (uint32_t)(mt * 16 * KC) + a_k[ks]);
                uint32_t bf[8][2];
#pragma unroll
                for (int j = 0; j < 4; j++)
                    ldsm_x4(bf[2 * j][0], bf[2 * j][1],
                            bf[2 * j + 1][0], bf[2 * j + 1][1],
                            b_ln + (uint32_t)(j * 16 * KC) + b_k[ks]);
#pragma unroll
                for (int mt = 0; mt < 4; mt++)
#pragma unroll
                    for (int nt = 0; nt < 8; nt++)
                        mma_fp8(acc[mt][nt], af[mt], bf[nt]);
            }
        }
    }

    // ---- epilogue: dequant (in_scale * weight_scale) + bias ----
    int gid = lane >> 2;
    int tig = lane & 3;
#pragma unroll
    for (int mt = 0; mt < 4; mt++) {
        int r0 = m0 + wm * 64 + mt * 16 + gid;
        int r1 = r0 + 8;
        float is0 = g_in_scale[r0];
        float is1 = g_in_scale[r1];
        float* o0 = out + (size_t)r0 * N + n0;
        float* o1 = out + (size_t)r1 * N + n0;
#pragma unroll
        for (int nt = 0; nt < 8; nt++) {
            int c = wn * 64 + nt * 8 + tig * 2;
            float2 ws = *reinterpret_cast<const float2*>(wscale + n0 + c);
            float2 bi = *reinterpret_cast<const float2*>(bias + n0 + c);
            float2 v0, v1;
            v0.x = acc[mt][nt][0] * is0 * ws.x + bi.x;
            v0.y = acc[mt][nt][1] * is0 * ws.y + bi.y;
            v1.x = acc[mt][nt][2] * is1 * ws.x + bi.x;
            v1.y = acc[mt][nt][3] * is1 * ws.y + bi.y;
            *reinterpret_cast<float2*>(o0 + c) = v0;
            *reinterpret_cast<float2*>(o1 + c) = v1;
        }
    }
}

// ============================================================
// Launch
// ============================================================
extern "C" void kernel_launch(void* const* d_in, const int* in_sizes, int n_in,
                              void* d_out, int out_size)
{
    const float*   x  = (const float*)d_in[0];
    const void*    w  = d_in[1];
    const float*   ws = (const float*)d_in[2];
    const float*   b  = (const float*)d_in[3];
    float* out = (float*)d_out;

    int N = in_sizes[2];
    long long WE = in_sizes[1];
    int K = (int)(WE / N);
    int T = in_sizes[0] / K;

    detect_kernel<<<1, 256>>>(w);
    prep_kernel<<<(int)((WE / 16 + 255) / 256), 256>>>(w, WE);
    quant_kernel<<<T, 256>>>(x, K);

    cudaFuncSetAttribute(gemm_kernel, cudaFuncAttributeMaxDynamicSharedMemorySize,
                         SMEM_TOTAL);
    dim3 grid(N / TN, T / TM);
    gemm_kernel<<<grid, 256, SMEM_TOTAL>>>((const uint8_t*)w, ws, b, out, T, K, N);
}

// round 9
// speedup vs baseline: 1.0539x; 1.0054x over previous
#include <cuda_runtime.h>
#include <cuda_fp8.h>
#include <cuda_bf16.h>
#include <cstdint>

// ============================================================
// Scratch (device globals: allocation-guard-safe)
// ============================================================
static __device__ uint8_t g_xq[8192ull * 4096ull];     // quantized activations
static __device__ uint8_t g_wq[4096ull * 4096ull];     // re-encoded weights (f32/bf16 modes)
static __device__ float   g_in_scale[8192];            // per-token scales
static __device__ int     g_wmode;                     // 0=raw fp8 bytes, 1=f32, 2=bf16

// ============================================================
// Helpers
// ============================================================
#define SW128(o) ((o) ^ (((o) >> 3) & 0x70))

__device__ __forceinline__ uint32_t smem_u32(const void* p) {
    uint32_t a;
    asm("{ .reg .u64 t; cvta.to.shared.u64 t, %1; cvt.u32.u64 %0, t; }"
        : "=r"(a) : "l"(p));
    return a;
}

__device__ __forceinline__ void cp16(uint32_t dst, const void* src) {
    asm volatile("cp.async.cg.shared.global [%0], [%1], 16;\n"
                 :: "r"(dst), "l"(src));
}

__device__ __forceinline__ void ldsm_x4(uint32_t& r0, uint32_t& r1,
                                        uint32_t& r2, uint32_t& r3, uint32_t addr) {
    asm volatile("ldmatrix.sync.aligned.m8n8.x4.shared.b16 {%0,%1,%2,%3}, [%4];"
                 : "=r"(r0), "=r"(r1), "=r"(r2), "=r"(r3) : "r"(addr));
}

// FP8 e4m3 MMA, m16n8k32, f32 accumulate
__device__ __forceinline__ void mma_fp8(float* d, const uint32_t* a, const uint32_t* b) {
    asm volatile(
        "mma.sync.aligned.m16n8k32.row.col.f32.e4m3.e4m3.f32 "
        "{%0,%1,%2,%3}, {%4,%5,%6,%7}, {%8,%9}, {%0,%1,%2,%3};"
        : "+f"(d[0]), "+f"(d[1]), "+f"(d[2]), "+f"(d[3])
        : "r"(a[0]), "r"(a[1]), "r"(a[2]), "r"(a[3]), "r"(b[0]), "r"(b[1]));
}

// ============================================================
// Kernel 0: detect weight storage format (1 block, 256 threads)
// ============================================================
__global__ void detect_kernel(const void* w) {
    __shared__ int okf, bigf, okh, bigh;
    int t = threadIdx.x;
    if (t == 0) { okf = 0; bigf = 0; okh = 0; bigh = 0; }
    __syncthreads();

    float vf = reinterpret_cast<const float*>(w)[t];
    float af = fabsf(vf);
    if (af <= 448.0f) {
        atomicAdd(&okf, 1);
        if (af >= 0.5f) atomicAdd(&bigf, 1);
    }
    float vh = __bfloat162float(reinterpret_cast<const __nv_bfloat16*>(w)[t]);
    float ah = fabsf(vh);
    if (ah <= 448.0f) {
        atomicAdd(&okh, 1);
        if (ah >= 0.5f) atomicAdd(&bigh, 1);
    }
    __syncthreads();
    if (t == 0) {
        int m = 0;
        if (okf == 256 && bigf >= 128)      m = 1;
        else if (okh == 256 && bigh >= 128) m = 2;
        g_wmode = m;
    }
}

// ============================================================
// Kernel 1: FUSED activation quant (blocks [0,T)) +
//           weight re-encode (blocks [T, T+WB))
//   Both memory-bound; fused so their DRAM traffic overlaps.
// ============================================================
__global__ __launch_bounds__(256) void fused_prep_quant(
    const float* __restrict__ x, const void* __restrict__ w,
    int K, int T, long long WE)
{
    int b = blockIdx.x;
    int t = threadIdx.x;

    if (b < T) {
        // ---- per-token dynamic FP8 quantization (row = b) ----
        const float4* xr = reinterpret_cast<const float4*>(x + (size_t)b * K);
        int nv = K >> 10;

        float vals[16];
        float amax = 0.0f;
#pragma unroll
        for (int i = 0; i < 4; i++) {
            if (i < nv) {
                float4 v = xr[t + (i << 8)];
                vals[4 * i + 0] = v.x; vals[4 * i + 1] = v.y;
                vals[4 * i + 2] = v.z; vals[4 * i + 3] = v.w;
                amax = fmaxf(amax, fmaxf(fmaxf(fabsf(v.x), fabsf(v.y)),
                                         fmaxf(fabsf(v.z), fabsf(v.w))));
            }
        }
#pragma unroll
        for (int o = 16; o > 0; o >>= 1)
            amax = fmaxf(amax, __shfl_xor_sync(0xffffffffu, amax, o));

        __shared__ float red[8];
        __shared__ float s_scale;
        if ((t & 31) == 0) red[t >> 5] = amax;
        __syncthreads();
        if (t == 0) {
            float a = red[0];
#pragma unroll
            for (int i = 1; i < 8; i++) a = fmaxf(a, red[i]);
            float s = fmaxf(a / 448.0f, 1e-12f);   // exact IEEE div, matches reference
            s_scale = s;
            g_in_scale[b] = s;
        }
        __syncthreads();
        float s = s_scale;

        uint32_t* ow = reinterpret_cast<uint32_t*>(g_xq + (size_t)b * K);
#pragma unroll
        for (int i = 0; i < 4; i++) {
            if (i < nv) {
                uint32_t p = 0;
#pragma unroll
                for (int j = 0; j < 4; j++) {
                    float q = vals[4 * i + j] / s;       // exact IEEE div
                    __nv_fp8_e4m3 f8 = __nv_fp8_e4m3(q); // RN + satfinite
                    p |= ((uint32_t)f8.__x) << (8 * j);
                }
                ow[t + (i << 8)] = p;
            }
        }
    } else {
        // ---- weight re-encode to e4m3 bytes (modes 1/2 only) ----
        int mode = g_wmode;
        if (mode == 0) return;
        long long e0 = (long long)((b - T) * 256 + t) * 16;
        if (e0 >= WE) return;

        uint8_t bb[16];
        if (mode == 1) {
            const float4* f4 = reinterpret_cast<const float4*>(w) + (e0 >> 2);
#pragma unroll
            for (int j = 0; j < 4; j++) {
                float4 v = f4[j];
                bb[4 * j + 0] = __nv_fp8_e4m3(v.x).__x;
                bb[4 * j + 1] = __nv_fp8_e4m3(v.y).__x;
                bb[4 * j + 2] = __nv_fp8_e4m3(v.z).__x;
                bb[4 * j + 3] = __nv_fp8_e4m3(v.w).__x;
            }
        } else {
            const __nv_bfloat16* h = reinterpret_cast<const __nv_bfloat16*>(w) + e0;
#pragma unroll
            for (int j = 0; j < 16; j++)
                bb[j] = __nv_fp8_e4m3(__bfloat162float(h[j])).__x;
        }
        *reinterpret_cast<uint4*>(g_wq + e0) = *reinterpret_cast<const uint4*>(bb);
    }
}

// ============================================================
// Kernel 2: FP8 GEMM via mma.sync.m16n8k32.e4m3  (unchanged R8)
//   CTA 128x256, 8 warps (2x4), warp tile 64x64, 1 CTA/SM
//   2-stage x 256B-K pipeline (2 chunks/stage), SW128 SMEM
// ============================================================
#define TM 128
#define TN 256
#define KC 128
#define CHUNK_BYTES ((TM + TN) * KC)                  // 49152
#define STAGE_BYTES (2 * CHUNK_BYTES)                 // 98304
#define SMEM_TOTAL (2 * STAGE_BYTES)                  // 196608

__global__ __launch_bounds__(256, 1) void gemm_kernel(
    const uint8_t* __restrict__ Win, const float* __restrict__ wscale,
    const float* __restrict__ bias, float* __restrict__ out,
    int T, int K, int N)
{
    extern __shared__ __align__(1024) char smem[];
    uint32_t smem_base = smem_u32(smem);
    int tid = threadIdx.x;
    int wid = tid >> 5;
    int lane = tid & 31;

    const uint8_t* W = g_wmode ? g_wq : Win;

    int m0 = blockIdx.y * TM;
    int n0 = blockIdx.x * TN;
    int nc2 = K >> 8;           // 256B K-superchunks

    int wm = wid >> 2;
    int wn = wid & 3;

    // ---- hoisted global-load addressing ----
    int lr = tid >> 3;
    int lc = (tid & 7) * 16;
    uint32_t sw = SW128((uint32_t)(lr * KC + lc));
    const uint8_t* aPtr = g_xq + (size_t)(m0 + lr) * K + lc;
    const uint8_t* bPtr = W + (size_t)(n0 + lr) * K + lc;
    size_t rs32 = (size_t)32 * K;

#define LOAD_STAGE(s_, kc2_) do {                                              \
        _Pragma("unroll")                                                      \
        for (int c = 0; c < 2; c++) {                                          \
            uint32_t ad = smem_base + (s_) * STAGE_BYTES + c * CHUNK_BYTES + sw; \
            uint32_t bd = ad + TM * KC;                                        \
            const uint8_t* ag = aPtr + (size_t)(2 * (kc2_) + c) * KC;          \
            const uint8_t* bg = bPtr + (size_t)(2 * (kc2_) + c) * KC;          \
            _Pragma("unroll")                                                  \
            for (int i = 0; i < 4; i++)                                        \
                cp16(ad + (uint32_t)(i * 4096), ag + i * rs32);                \
            _Pragma("unroll")                                                  \
            for (int i = 0; i < 8; i++)                                        \
                cp16(bd + (uint32_t)(i * 4096), bg + i * rs32);                \
        }                                                                      \
        asm volatile("cp.async.commit_group;\n" ::);                           \
    } while (0)

    // ---- hoisted ldmatrix addressing (algebraic SW128) ----
    int a_row = wm * 64 + (lane & 15);
    uint32_t a_roff = (uint32_t)(a_row * KC);
    uint32_t a_sel = (uint32_t)((lane >> 4) << 4);
    uint32_t kxor = (uint32_t)((lane & 7) << 4);
    int b_rowl = (lane & 7) + ((lane >> 4) << 3);
    uint32_t b_roff = (uint32_t)((wn * 64 + b_rowl) * KC);
    uint32_t b_sel = (uint32_t)(((lane >> 3) & 1) << 4);

    uint32_t a_k[4], b_k[4];
#pragma unroll
    for (int ks = 0; ks < 4; ks++) {
        a_k[ks] = ((uint32_t)(ks * 32) + a_sel) ^ kxor;
        b_k[ks] = ((uint32_t)(ks * 32) + b_sel) ^ kxor;
    }

    float acc[4][8][4];
#pragma unroll
    for (int i = 0; i < 4; i++)
#pragma unroll
        for (int j = 0; j < 8; j++)
#pragma unroll
            for (int k = 0; k < 4; k++) acc[i][j][k] = 0.0f;

    LOAD_STAGE(0, 0);

    for (int kc2 = 0; kc2 < nc2; kc2++) {
        int s = kc2 & 1;
        asm volatile("cp.async.wait_group 0;\n" ::: "memory");
        __syncthreads();

        if (kc2 + 1 < nc2) LOAD_STAGE(s ^ 1, kc2 + 1);

#pragma unroll
        for (int c = 0; c < 2; c++) {
            uint32_t cbase = smem_base + s * STAGE_BYTES + c * CHUNK_BYTES;
            uint32_t a_ln = cbase + a_roff;
            uint32_t b_ln = cbase + TM * KC + b_roff;

#pragma unroll
            for (int ks = 0; ks < 4; ks++) {
                uint32_t bf[8][2];
#pragma unroll
                for (int j = 0; j < 4; j++)
                    ldsm_x4(bf[2 * j][0], bf[2 * j][1],
                            bf[2 * j + 1][0], bf[2 * j + 1][1],
                            b_ln + (uint32_t)(j * 16 * KC) + b_k[ks]);
                uint32_t af[4][4];
#pragma unroll
                for (int mt = 0; mt < 4; mt++)
                    ldsm_x4(af[mt][0], af[mt][1], af[mt][2], af[mt][3],
                            a_ln + (uint32_t)(mt * 16 * KC) + a_k[ks]);
#pragma unroll
                for (int mt = 0; mt < 4; mt++)
#pragma unroll
                    for (int nt = 0; nt < 8; nt++)
                        mma_fp8(acc[mt][nt], af[mt], bf[nt]);
            }
        }
    }

    // ---- epilogue: dequant (in_scale * weight_scale) + bias ----
    int gid = lane >> 2;
    int tig = lane & 3;
#pragma unroll
    for (int mt = 0; mt < 4; mt++) {
        int r0 = m0 + wm * 64 + mt * 16 + gid;
        int r1 = r0 + 8;
        float is0 = g_in_scale[r0];
        float is1 = g_in_scale[r1];
        float* o0 = out + (size_t)r0 * N + n0;
        float* o1 = out + (size_t)r1 * N + n0;
#pragma unroll
        for (int nt = 0; nt < 8; nt++) {
            int c = wn * 64 + nt * 8 + tig * 2;
            float2 ws = *reinterpret_cast<const float2*>(wscale + n0 + c);
            float2 bi = *reinterpret_cast<const float2*>(bias + n0 + c);
            float2 v0, v1;
            v0.x = acc[mt][nt][0] * is0 * ws.x + bi.x;
            v0.y = acc[mt][nt][1] * is0 * ws.y + bi.y;
            v1.x = acc[mt][nt][2] * is1 * ws.x + bi.x;
            v1.y = acc[mt][nt][3] * is1 * ws.y + bi.y;
            *reinterpret_cast<float2*>(o0 + c) = v0;
            *reinterpret_cast<float2*>(o1 + c) = v1;
        }
    }
}

// ============================================================
// Launch
// ============================================================
extern "C" void kernel_launch(void* const* d_in, const int* in_sizes, int n_in,
                              void* d_out, int out_size)
{
    const float*   x  = (const float*)d_in[0];
    const void*    w  = d_in[1];
    const float*   ws = (const float*)d_in[2];
    const float*   b  = (const float*)d_in[3];
    float* out = (float*)d_out;

    int N = in_sizes[2];
    long long WE = in_sizes[1];
    int K = (int)(WE / N);
    int T = in_sizes[0] / K;

    detect_kernel<<<1, 256>>>(w);

    int wBlocks = (int)((WE / 16 + 255) / 256);
    fused_prep_quant<<<T + wBlocks, 256>>>(x, w, K, T, WE);

    cudaFuncSetAttribute(gemm_kernel, cudaFuncAttributeMaxDynamicSharedMemorySize,
                         SMEM_TOTAL);
    dim3 grid(N / TN, T / TM);
    gemm_kernel<<<grid, 256, SMEM_TOTAL>>>((const uint8_t*)w, ws, b, out, T, K, N);
}